// round 15
// baseline (speedup 1.0000x reference)
#include <cuda_runtime.h>

#define CHN   4
#define HHT   128
#define WWD   128
#define TT    50
#define TP    52          // conv3 padded t-stride (t-quad LDS.128)
#define SOP   52          // staging row stride (floats), float2 aligned
#define NBATCH 8
#define AW2   132         // bufA plane width/height (PAD=2 halo)
#define BW2   130         // bufB plane width/height (PAD=1 halo)
#define NPLANE (NBATCH*CHN)   // 32

__device__ float g_bufA[NPLANE * AW2 * AW2 * TT];
__device__ float g_bufB[NPLANE * BW2 * BW2 * TT];

typedef unsigned long long u64;

__constant__ ulonglong2 c_w5d[200];
__constant__ ulonglong2 c_w3d[72];
__device__ float4 g_wpack[272];

template <int K>
__device__ __forceinline__ ulonglong2 cwload(int i);
template <>
__device__ __forceinline__ ulonglong2 cwload<5>(int i) { return c_w5d[i]; }
template <>
__device__ __forceinline__ ulonglong2 cwload<3>(int i) { return c_w3d[i]; }

__device__ __forceinline__ void fma2(u64& d, u64 a, u64 b) {
    asm("fma.rn.f32x2 %0, %1, %2, %0;" : "+l"(d) : "l"(a), "l"(b));
}
__device__ __forceinline__ float2 upk(u64 v) {
    float2 f;
    f.x = __uint_as_float((unsigned)(v & 0xffffffffull));
    f.y = __uint_as_float((unsigned)(v >> 32));
    return f;
}

#define WAITG(n) asm volatile("cp.async.wait_group %0;" :: "n"(n) : "memory")

// Merged setup kernel: block 0 packs weights; blocks 1..64 zero buffer halos.
__global__ void setup_kernel(const float* __restrict__ w1,
                             const float* __restrict__ w2) {
    if (blockIdx.x == 0) {
        int tid = threadIdx.x;
        if (tid < 100) {
            float a = w1[tid], b = w1[100 + tid], c = w1[200 + tid], d = w1[300 + tid];
            g_wpack[tid * 2 + 0] = make_float4(a, a, b, b);
            g_wpack[tid * 2 + 1] = make_float4(c, c, d, d);
        }
        if (tid >= 128 && tid < 164) {
            int t = tid - 128;
            float a = w2[t], b = w2[36 + t], c = w2[72 + t], d = w2[108 + t];
            g_wpack[200 + t * 2 + 0] = make_float4(a, a, b, b);
            g_wpack[200 + t * 2 + 1] = make_float4(c, c, d, d);
        }
        return;
    }
    int bid = blockIdx.x - 1;
    float* buf;
    int W2, P, plane;
    if (bid < NPLANE) { buf = g_bufA; W2 = AW2; P = 2; plane = bid; }
    else              { buf = g_bufB; W2 = BW2; P = 1; plane = bid - NPLANE; }
    const int H2 = W2;
    float2* base = reinterpret_cast<float2*>(buf + (long)plane * H2 * W2 * TT);
    const int strip = P * W2 * TT / 2;
    const float2 z = make_float2(0.f, 0.f);
    float2* bot = base + (long)(H2 - P) * W2 * (TT / 2);
    for (int i = threadIdx.x; i < strip; i += blockDim.x) {
        base[i] = z;
        bot[i]  = z;
    }
    const int ch = P * TT / 2;
    const int nrows = H2 - 2 * P;
    for (int idx = threadIdx.x; idx < nrows * 2 * ch; idx += blockDim.x) {
        int row = idx / (2 * ch);
        int rem = idx - row * (2 * ch);
        int side = rem / ch;
        int off  = rem - side * ch;
        float2* p = base + (long)(P + row) * W2 * (TT / 2)
                         + (side ? (W2 - P) * (TT / 2) : 0);
        p[off] = z;
    }
}

// ---------------------------------------------------------------------------
// Standalone alpha-PSP (layer 1): unpadded input -> padded bufA interior.
// ---------------------------------------------------------------------------
#define PW_PAD 53

__global__ void __launch_bounds__(128, 8) psp_kernel(const float* __restrict__ in,
                                                     float* __restrict__ out,
                                                     float r, float coef) {
    __shared__ float sm[4 * 32 * PW_PAD];
    const int lane = threadIdx.x & 31;
    const int wrp  = threadIdx.x >> 5;
    const int h    = blockIdx.x;
    const int nc   = blockIdx.y;
    float* ws = sm + wrp * 32 * PW_PAD;
    const float* g = in + (((long)nc * HHT + h) * WWD + wrp * 32) * TT;
    float* o = out + (((long)nc * AW2 + h + 2) * AW2 + (wrp * 32 + 2)) * TT;
#pragma unroll
    for (int w = 0; w < 32; ++w) {
        ws[w * PW_PAD + lane] = g[w * TT + lane];
        if (lane < TT - 32) ws[w * PW_PAD + 32 + lane] = g[w * TT + 32 + lane];
    }
    __syncwarp();
    float* row = ws + lane * PW_PAD;
    float s1 = 0.f, s2 = 0.f;
#pragma unroll
    for (int t = 0; t < TT; ++t) {
        float x = row[t];
        row[t] = coef * s2;
        s1 = fmaf(r, s1, x);
        s2 = fmaf(r, s2, r * s1);
    }
    __syncwarp();
#pragma unroll
    for (int w = 0; w < 32; ++w) {
        o[w * TT + lane] = ws[w * PW_PAD + lane];
        if (lane < TT - 32) o[w * TT + 32 + lane] = ws[w * PW_PAD + 32 + lane];
    }
}

// ---------------------------------------------------------------------------
// conv5 + spike + psp epilogue: 4-OUTPUT-ROW blocking, t-pair threads.
// 800 thr = 25 warps; thread = (w=lane, t-pair t0=2*wrp), acc[4hs][4co].
// TPP=TT=50: natural stride, LDS.64 conflict-free (25 odd), no fill padding.
// Per (ci,kw): 8 input row loads feed 16 FMAs/float; weight LDC CSE x4.
// cp.async double-buffered over ci. 1 block/SM (smem 115.2 KB).
// ---------------------------------------------------------------------------
__global__ void __launch_bounds__(800, 1)
conv5_kernel(const float* __restrict__ in, float* __restrict__ out,
             float rR, float cR, float theta, float rP, float cP) {
    constexpr int K     = 5;
    constexpr int WH    = 36;            // 32 + K-1
    constexpr int NR    = 8;             // input rows for 4 output rows
    constexpr int TPP   = 50;            // natural t stride
    constexpr int STAGE = NR * WH * TPP; // 14400 floats

    extern __shared__ float sm[];
    const unsigned smem_base = (unsigned)__cvta_generic_to_shared(sm);

    const int tid  = threadIdx.x;
    const int lane = tid & 31;
    const int wrp  = tid >> 5;           // 0..24
    const int w0   = blockIdx.x * 32;
    const int h0   = blockIdx.y * 4;     // first output row (padded coords)
    const int n    = blockIdx.z;
    const int t0   = wrp * 2;            // t-pair

    auto fill = [&](int buf, int ci) {
        if (lane < 25) {
            const unsigned dstb = smem_base + buf * (STAGE * 4) + lane * 8;
            const int nc = n * CHN + ci;
#pragma unroll
            for (int r = 0; r < NR; ++r) {
                const char* srcb = (const char*)(in +
                    (((long)nc * AW2 + h0 + r) * AW2 + w0) * TT) + lane * 8;
#pragma unroll
                for (int rr = 0; rr < 2; ++rr) {
                    const int wr = wrp + rr * 25;
                    if (wr < WH) {
                        asm volatile("cp.async.ca.shared.global [%0], [%1], 8;"
                                     :: "r"(dstb + (r * WH + wr) * (TPP * 4)),
                                        "l"(srcb + wr * (TT * 4)) : "memory");
                    }
                }
            }
        }
        asm volatile("cp.async.commit_group;" ::: "memory");
    };

    u64 acc[4][4];   // [hs][co], each = (t0, t0+1)
#pragma unroll
    for (int s = 0; s < 4; ++s)
#pragma unroll
        for (int c = 0; c < 4; ++c) acc[s][c] = 0ull;

    fill(0, 0);
    WAITG(0);
    __syncthreads();

#pragma unroll
    for (int ci = 0; ci < CHN; ++ci) {
        if (ci < CHN - 1) fill((ci + 1) & 1, ci + 1);
        const float* s_in = sm + (ci & 1) * STAGE;
#pragma unroll
        for (int kw = 0; kw < K; ++kw) {
            u64 iv[NR];
#pragma unroll
            for (int r = 0; r < NR; ++r)
                iv[r] = *reinterpret_cast<const u64*>(
                    s_in + (r * WH + lane + kw) * TPP + t0);
#pragma unroll
            for (int r = 0; r < NR; ++r) {
#pragma unroll
                for (int hs = 0; hs < 4; ++hs) {
                    const int kh = r - hs;
                    if (kh >= 0 && kh < K) {
                        const int tap = (ci * K + kh) * K + kw;
                        const ulonglong2 wa = cwload<5>(tap * 2);
                        const ulonglong2 wb = cwload<5>(tap * 2 + 1);
                        fma2(acc[hs][0], iv[r], wa.x);
                        fma2(acc[hs][1], iv[r], wa.y);
                        fma2(acc[hs][2], iv[r], wb.x);
                        fma2(acc[hs][3], iv[r], wb.y);
                    }
                }
            }
        }
        if (ci < CHN - 1) {
            WAITG(0);
            __syncthreads();
        }
    }
    __syncthreads();

    // stage: s_out[(hs*4+co)*32 + w][SOP], float2 stores (8B aligned)
    float* s_out = sm;   // overlay: 512*52*4 = 106.5 KB <= 115.2 KB
#pragma unroll
    for (int hs = 0; hs < 4; ++hs)
#pragma unroll
        for (int co = 0; co < 4; ++co) {
            float* p = s_out + ((hs * 4 + co) * 32 + lane) * SOP + t0;
            *reinterpret_cast<float2*>(p) = upk(acc[hs][co]);
        }
    __syncthreads();

    // fused spike + next-layer psp epilogue: 512 pixels
    if (tid < 512) {
        float* row = s_out + tid * SOP;
        float sd1 = 0.f, sd2 = 0.f, sp1 = 0.f, sp2 = 0.f;
#pragma unroll
        for (int t = 0; t < TT; ++t) {
            float m = fmaf(cR, sd2, row[t]);
            float s = (m >= theta) ? 1.f : 0.f;
            sd1 = fmaf(rR, sd1, s);
            sd2 = fmaf(rR, sd2, rR * sd1);
            row[t] = cP * sp2;
            sp1 = fmaf(rP, sp1, s);
            sp2 = fmaf(rP, sp2, rP * sp1);
        }
    }
    __syncthreads();

    // coalesced store into padded bufB: 4hs x 4co x 32w x 50t
    if (lane < 25) {
#pragma unroll
        for (int hs = 0; hs < 4; ++hs)
#pragma unroll
            for (int co = 0; co < 4; ++co) {
                const float2* s2 = reinterpret_cast<const float2*>(
                    s_out + (hs * 4 + co) * 32 * SOP);
                float2* g2 = reinterpret_cast<float2*>(out +
                    (((long)(n * CHN + co) * BW2 + h0 + hs + 1) * BW2 +
                     (w0 + 1)) * TT);
                for (int w = wrp; w < 32; w += 25)
                    g2[w * (TT / 2) + lane] = s2[w * (SOP / 2) + lane];
            }
    }
}

// ---------------------------------------------------------------------------
// conv3 + spike-out: unchanged R14 structure (2-row, t-quad, 3-stage ring).
// ---------------------------------------------------------------------------
__global__ void __launch_bounds__(416, 2)
conv3_kernel(const float* __restrict__ in, float* __restrict__ out,
             float rR, float cR, float theta) {
    constexpr int K     = 3;
    constexpr int WH    = 34;
    constexpr int NR    = 4;
    constexpr int STAGE = NR * WH * TP;

    extern __shared__ float sm[];
    const unsigned smem_base = (unsigned)__cvta_generic_to_shared(sm);

    const int tid  = threadIdx.x;
    const int lane = tid & 31;
    const int wrp  = tid >> 5;
    const int w0   = blockIdx.x * 32;
    const int h0   = blockIdx.y * 2;
    const int n    = blockIdx.z;
    const int t0   = wrp * 4;

    auto fill = [&](int buf, int ci) {
        if (lane < 25) {
            const unsigned dstb = smem_base + buf * (STAGE * 4) + lane * 8;
            const int nc = n * CHN + ci;
#pragma unroll
            for (int r = 0; r < NR; ++r) {
                const char* srcb = (const char*)(in +
                    (((long)nc * BW2 + h0 + r) * BW2 + w0) * TT) + lane * 8;
#pragma unroll
                for (int rr = 0; rr < 3; ++rr) {
                    const int wr = wrp + rr * 13;
                    if (wr < WH) {
                        asm volatile("cp.async.ca.shared.global [%0], [%1], 8;"
                                     :: "r"(dstb + (r * WH + wr) * (TP * 4)),
                                        "l"(srcb + wr * (TT * 4)) : "memory");
                    }
                }
            }
        }
        asm volatile("cp.async.commit_group;" ::: "memory");
    };

    u64 acc[2][4][2];
#pragma unroll
    for (int s = 0; s < 2; ++s)
#pragma unroll
        for (int c = 0; c < 4; ++c) { acc[s][c][0] = 0ull; acc[s][c][1] = 0ull; }

    auto compute = [&](const float* s_in, int ci) {
#pragma unroll
        for (int kw = 0; kw < K; ++kw) {
            const float* colp = s_in + (lane + kw) * TP + t0;
            ulonglong2 iv[NR];
#pragma unroll
            for (int r = 0; r < NR; ++r)
                iv[r] = *reinterpret_cast<const ulonglong2*>(colp + r * WH * TP);
#pragma unroll
            for (int r = 0; r < NR; ++r) {
                if (r < K) {
                    const int tap = (ci * K + r) * K + kw;
                    const ulonglong2 wa = cwload<3>(tap * 2);
                    const ulonglong2 wb = cwload<3>(tap * 2 + 1);
                    fma2(acc[0][0][0], iv[r].x, wa.x);
                    fma2(acc[0][0][1], iv[r].y, wa.x);
                    fma2(acc[0][1][0], iv[r].x, wa.y);
                    fma2(acc[0][1][1], iv[r].y, wa.y);
                    fma2(acc[0][2][0], iv[r].x, wb.x);
                    fma2(acc[0][2][1], iv[r].y, wb.x);
                    fma2(acc[0][3][0], iv[r].x, wb.y);
                    fma2(acc[0][3][1], iv[r].y, wb.y);
                }
                if (r >= 1) {
                    const int tap = (ci * K + (r - 1)) * K + kw;
                    const ulonglong2 wa = cwload<3>(tap * 2);
                    const ulonglong2 wb = cwload<3>(tap * 2 + 1);
                    fma2(acc[1][0][0], iv[r].x, wa.x);
                    fma2(acc[1][0][1], iv[r].y, wa.x);
                    fma2(acc[1][1][0], iv[r].x, wa.y);
                    fma2(acc[1][1][1], iv[r].y, wa.y);
                    fma2(acc[1][2][0], iv[r].x, wb.x);
                    fma2(acc[1][2][1], iv[r].y, wb.x);
                    fma2(acc[1][3][0], iv[r].x, wb.y);
                    fma2(acc[1][3][1], iv[r].y, wb.y);
                }
            }
        }
    };

    // 3-stage ring: 2 ci in flight
    fill(0, 0);
    fill(1, 1);
    WAITG(1);
    __syncthreads();
#pragma unroll
    for (int ci = 0; ci < CHN; ++ci) {
        if (ci + 2 < CHN) fill((ci + 2) % 3, ci + 2);
        compute(sm + (ci % 3) * STAGE, ci);
        if (ci < CHN - 1) {
            if (ci + 2 < CHN) WAITG(1);
            else              WAITG(0);
            __syncthreads();
        }
    }
    __syncthreads();

    float* s_out = sm;
#pragma unroll
    for (int hs = 0; hs < 2; ++hs)
#pragma unroll
        for (int co = 0; co < 4; ++co) {
            float* p = s_out + ((hs * 4 + co) * 32 + lane) * SOP + t0;
            *reinterpret_cast<float2*>(p) = upk(acc[hs][co][0]);
            if (t0 + 2 < TT)
                *reinterpret_cast<float2*>(p + 2) = upk(acc[hs][co][1]);
        }
    __syncthreads();

    if (tid < 256) {
        float* row = s_out + tid * SOP;
        float sd1 = 0.f, sd2 = 0.f;
#pragma unroll
        for (int t = 0; t < TT; ++t) {
            float m = fmaf(cR, sd2, row[t]);
            float s = (m >= theta) ? 1.f : 0.f;
            sd1 = fmaf(rR, sd1, s);
            sd2 = fmaf(rR, sd2, rR * sd1);
            row[t] = s;
        }
    }
    __syncthreads();

    if (lane < 25) {
#pragma unroll
        for (int hs = 0; hs < 2; ++hs)
#pragma unroll
            for (int co = 0; co < 4; ++co) {
                const float2* s2 = reinterpret_cast<const float2*>(
                    s_out + (hs * 4 + co) * 32 * SOP);
                float2* g2 = reinterpret_cast<float2*>(out +
                    (((long)(n * CHN + co) * WWD + h0 + hs) * WWD + w0) * TT);
#pragma unroll
                for (int rr = 0; rr < 3; ++rr) {
                    const int w = wrp + rr * 13;
                    if (w < 32) g2[w * (TT / 2) + lane] = s2[w * (SOP / 2) + lane];
                }
            }
    }
}

// ---------------------------------------------------------------------------

extern "C" void kernel_launch(void* const* d_in, const int* in_sizes, int n_in,
                              void* d_out, int out_size) {
    const float* x  = (const float*)d_in[0];
    const float* w1 = (const float*)d_in[1];
    const float* w2 = (const float*)d_in[2];
    float* outp = (float*)d_out;

    float *bufA, *bufB;
    cudaGetSymbolAddress((void**)&bufA, g_bufA);
    cudaGetSymbolAddress((void**)&bufB, g_bufB);
    float4* wpack;
    cudaGetSymbolAddress((void**)&wpack, g_wpack);

    const int SMEM5 = 2 * 8 * 36 * 50 * 4;   // 115200 B -> 1 block/SM
    const int SMEM3 = 3 * 4 * 34 * TP * 4;   //  84864 B -> 2 blocks/SM
    cudaFuncSetAttribute((const void*)conv5_kernel,
                         cudaFuncAttributeMaxDynamicSharedMemorySize, SMEM5);
    cudaFuncSetAttribute((const void*)conv3_kernel,
                         cudaFuncAttributeMaxDynamicSharedMemorySize, SMEM3);

    const float r1  = (float)0.36787944117144233;   // exp(-1/tau1)
    const float cP1 = (float)2.718281828459045;     // e/tau1
    const float rR1 = (float)0.36787944117144233;   // exp(-1/tauRef1)
    const float cR1 = (float)(-54.365636569180902); // -scaleRef*theta1*e/tauRef1
    const float th1 = 20.0f;
    const float r2  = (float)0.6065306597126334;    // exp(-1/tau2)
    const float cP2 = (float)1.3591409142295225;    // e/tau2
    const float rR2 = (float)0.6065306597126334;    // exp(-1/tauRef2)
    const float cR2 = (float)(-54.365636569180902); // -scaleRef*theta2*e/tauRef2
    const float th2 = 40.0f;

    dim3 pgrid(HHT, NPLANE);                    // (128, 32)
    dim3 c5grid(WWD / 32, HHT / 4, NBATCH);     // (4,32,8) = 1024 blocks
    dim3 c3grid(WWD / 32, HHT / 2, NBATCH);     // (4,64,8) = 2048 blocks

    setup_kernel<<<1 + 2 * NPLANE, 256>>>(w1, w2);
    cudaMemcpyToSymbolAsync(c_w5d, wpack, 200 * sizeof(float4), 0,
                            cudaMemcpyDeviceToDevice, 0);
    cudaMemcpyToSymbolAsync(c_w3d, wpack + 200, 72 * sizeof(float4), 0,
                            cudaMemcpyDeviceToDevice, 0);

    psp_kernel<<<pgrid, 128>>>(x, bufA, r1, cP1);
    conv5_kernel<<<c5grid, 800, SMEM5>>>(bufA, bufB, rR1, cR1, th1, r2, cP2);
    conv3_kernel<<<c3grid, 416, SMEM3>>>(bufB, outp, rR2, cR2, th2);
}

// round 16
// speedup vs baseline: 1.0311x; 1.0311x over previous
#include <cuda_runtime.h>

#define CHN   4
#define HHT   128
#define WWD   128
#define TT    50
#define TP    52          // conv padded t-stride (t-quad LDS.128), conflict-free
#define SOP   52          // staging row stride (floats), float2 aligned
#define NBATCH 8
#define AW2   132         // bufA plane width/height (PAD=2 halo)
#define BW2   130         // bufB plane width/height (PAD=1 halo)
#define NPLANE (NBATCH*CHN)   // 32

__device__ float g_bufA[NPLANE * AW2 * AW2 * TT];
__device__ float g_bufB[NPLANE * BW2 * BW2 * TT];

typedef unsigned long long u64;

// Pre-duplicated weights in constant memory.
// c_w5d[tap*2+0]=(w0,w0,w1,w1), [tap*2+1]=(w2,w2,w3,w3), tap=(ci*K+kh)*K+kw
__constant__ ulonglong2 c_w5d[200];
__constant__ ulonglong2 c_w3d[72];
__device__ float4 g_wpack[272];

template <int K>
__device__ __forceinline__ ulonglong2 cwload(int i);
template <>
__device__ __forceinline__ ulonglong2 cwload<5>(int i) { return c_w5d[i]; }
template <>
__device__ __forceinline__ ulonglong2 cwload<3>(int i) { return c_w3d[i]; }

__device__ __forceinline__ void fma2(u64& d, u64 a, u64 b) {
    asm("fma.rn.f32x2 %0, %1, %2, %0;" : "+l"(d) : "l"(a), "l"(b));
}
__device__ __forceinline__ float2 upk(u64 v) {
    float2 f;
    f.x = __uint_as_float((unsigned)(v & 0xffffffffull));
    f.y = __uint_as_float((unsigned)(v >> 32));
    return f;
}

#define WAITG(n) asm volatile("cp.async.wait_group %0;" :: "n"(n) : "memory")

// Setup: block 0 packs weights; blocks 1..512 zero buffer halos (8 sub-blocks
// per plane per buffer -> good SM coverage, ~2us).
__global__ void setup_kernel(const float* __restrict__ w1,
                             const float* __restrict__ w2) {
    if (blockIdx.x == 0) {
        int tid = threadIdx.x;
        if (tid < 100) {
            float a = w1[tid], b = w1[100 + tid], c = w1[200 + tid], d = w1[300 + tid];
            g_wpack[tid * 2 + 0] = make_float4(a, a, b, b);
            g_wpack[tid * 2 + 1] = make_float4(c, c, d, d);
        }
        if (tid >= 128 && tid < 164) {
            int t = tid - 128;
            float a = w2[t], b = w2[36 + t], c = w2[72 + t], d = w2[108 + t];
            g_wpack[200 + t * 2 + 0] = make_float4(a, a, b, b);
            g_wpack[200 + t * 2 + 1] = make_float4(c, c, d, d);
        }
        return;
    }
    const int bid  = blockIdx.x - 1;           // 0..511
    const int part = bid & 7;                   // 8 sub-blocks per plane
    const int pb   = bid >> 3;                  // 0..63
    float* buf;
    int W2, P, plane;
    if (pb < NPLANE) { buf = g_bufA; W2 = AW2; P = 2; plane = pb; }
    else             { buf = g_bufB; W2 = BW2; P = 1; plane = pb - NPLANE; }
    const int H2 = W2;
    float2* base = reinterpret_cast<float2*>(buf + (long)plane * H2 * W2 * TT);
    const float2 z = make_float2(0.f, 0.f);
    const int STRIDE = 8 * 256;
    const int off = part * 256 + threadIdx.x;
    // top + bottom strips
    const int strip = P * W2 * TT / 2;
    float2* bot = base + (long)(H2 - P) * W2 * (TT / 2);
    for (int i = off; i < strip; i += STRIDE) {
        base[i] = z;
        bot[i]  = z;
    }
    // side chunks: rows P..H2-P-1, left/right P pixels
    const int ch = P * TT / 2;
    const int nrows = H2 - 2 * P;
    for (int idx = off; idx < nrows * 2 * ch; idx += STRIDE) {
        int row = idx / (2 * ch);
        int rem = idx - row * (2 * ch);
        int side = rem / ch;
        int o2  = rem - side * ch;
        float2* p = base + (long)(P + row) * W2 * (TT / 2)
                         + (side ? (W2 - P) * (TT / 2) : 0);
        p[o2] = z;
    }
}

// ---------------------------------------------------------------------------
// Standalone alpha-PSP (layer 1): unpadded input -> padded bufA interior.
// float2 global accesses (25 active lanes), scalar conflict-free smem transpose.
// ---------------------------------------------------------------------------
#define PW_PAD 53

__global__ void __launch_bounds__(128, 8) psp_kernel(const float* __restrict__ in,
                                                     float* __restrict__ out,
                                                     float r, float coef) {
    __shared__ float sm[4 * 32 * PW_PAD];
    const int lane = threadIdx.x & 31;
    const int wrp  = threadIdx.x >> 5;
    const int h    = blockIdx.x;
    const int nc   = blockIdx.y;
    float* ws = sm + wrp * 32 * PW_PAD;
    const float2* g2 = reinterpret_cast<const float2*>(
        in + (((long)nc * HHT + h) * WWD + wrp * 32) * TT);
    float2* o2 = reinterpret_cast<float2*>(
        out + (((long)nc * AW2 + h + 2) * AW2 + (wrp * 32 + 2)) * TT);
    if (lane < 25) {
#pragma unroll
        for (int w = 0; w < 32; ++w) {
            float2 v = g2[w * (TT / 2) + lane];
            ws[w * PW_PAD + 2 * lane]     = v.x;
            ws[w * PW_PAD + 2 * lane + 1] = v.y;
        }
    }
    __syncwarp();
    float* row = ws + lane * PW_PAD;
    float s1 = 0.f, s2 = 0.f;
#pragma unroll
    for (int t = 0; t < TT; ++t) {
        float x = row[t];
        row[t] = coef * s2;
        s1 = fmaf(r, s1, x);
        s2 = fmaf(r, s2, r * s1);
    }
    __syncwarp();
    if (lane < 25) {
#pragma unroll
        for (int w = 0; w < 32; ++w) {
            float2 v;
            v.x = ws[w * PW_PAD + 2 * lane];
            v.y = ws[w * PW_PAD + 2 * lane + 1];
            o2[w * (TT / 2) + lane] = v;
        }
    }
}

// ---------------------------------------------------------------------------
// conv5 + spike + psp epilogue: R14 2-row t-quad, double buffer, occ 2.
// ---------------------------------------------------------------------------
__global__ void __launch_bounds__(416, 2)
conv5_kernel(const float* __restrict__ in, float* __restrict__ out,
             float rR, float cR, float theta, float rP, float cP) {
    constexpr int K     = 5;
    constexpr int WH    = 36;
    constexpr int NR    = 6;
    constexpr int STAGE = NR * WH * TP;

    extern __shared__ float sm[];
    const unsigned smem_base = (unsigned)__cvta_generic_to_shared(sm);

    const int tid  = threadIdx.x;
    const int lane = tid & 31;
    const int wrp  = tid >> 5;
    const int w0   = blockIdx.x * 32;
    const int h0   = blockIdx.y * 2;
    const int n    = blockIdx.z;
    const int t0   = wrp * 4;

    auto fill = [&](int buf, int ci) {
        if (lane < 25) {
            const unsigned dstb = smem_base + buf * (STAGE * 4) + lane * 8;
            const int nc = n * CHN + ci;
#pragma unroll
            for (int r = 0; r < NR; ++r) {
                const char* srcb = (const char*)(in +
                    (((long)nc * AW2 + h0 + r) * AW2 + w0) * TT) + lane * 8;
#pragma unroll
                for (int rr = 0; rr < 3; ++rr) {
                    const int wr = wrp + rr * 13;
                    if (wr < WH) {
                        asm volatile("cp.async.ca.shared.global [%0], [%1], 8;"
                                     :: "r"(dstb + (r * WH + wr) * (TP * 4)),
                                        "l"(srcb + wr * (TT * 4)) : "memory");
                    }
                }
            }
        }
        asm volatile("cp.async.commit_group;" ::: "memory");
    };

    u64 acc[2][4][2];
#pragma unroll
    for (int s = 0; s < 2; ++s)
#pragma unroll
        for (int c = 0; c < 4; ++c) { acc[s][c][0] = 0ull; acc[s][c][1] = 0ull; }

    fill(0, 0);
    WAITG(0);
    __syncthreads();

#pragma unroll
    for (int ci = 0; ci < CHN; ++ci) {
        if (ci < CHN - 1) fill((ci + 1) & 1, ci + 1);
        const float* s_in = sm + (ci & 1) * STAGE;
#pragma unroll
        for (int kw = 0; kw < K; ++kw) {
            const float* colp = s_in + (lane + kw) * TP + t0;
            ulonglong2 iv[NR];
#pragma unroll
            for (int r = 0; r < NR; ++r)
                iv[r] = *reinterpret_cast<const ulonglong2*>(colp + r * WH * TP);
#pragma unroll
            for (int r = 0; r < NR; ++r) {
                if (r < K) {
                    const int tap = (ci * K + r) * K + kw;
                    const ulonglong2 wa = cwload<5>(tap * 2);
                    const ulonglong2 wb = cwload<5>(tap * 2 + 1);
                    fma2(acc[0][0][0], iv[r].x, wa.x);
                    fma2(acc[0][0][1], iv[r].y, wa.x);
                    fma2(acc[0][1][0], iv[r].x, wa.y);
                    fma2(acc[0][1][1], iv[r].y, wa.y);
                    fma2(acc[0][2][0], iv[r].x, wb.x);
                    fma2(acc[0][2][1], iv[r].y, wb.x);
                    fma2(acc[0][3][0], iv[r].x, wb.y);
                    fma2(acc[0][3][1], iv[r].y, wb.y);
                }
                if (r >= 1) {
                    const int tap = (ci * K + (r - 1)) * K + kw;
                    const ulonglong2 wa = cwload<5>(tap * 2);
                    const ulonglong2 wb = cwload<5>(tap * 2 + 1);
                    fma2(acc[1][0][0], iv[r].x, wa.x);
                    fma2(acc[1][0][1], iv[r].y, wa.x);
                    fma2(acc[1][1][0], iv[r].x, wa.y);
                    fma2(acc[1][1][1], iv[r].y, wa.y);
                    fma2(acc[1][2][0], iv[r].x, wb.x);
                    fma2(acc[1][2][1], iv[r].y, wb.x);
                    fma2(acc[1][3][0], iv[r].x, wb.y);
                    fma2(acc[1][3][1], iv[r].y, wb.y);
                }
            }
        }
        if (ci < CHN - 1) {
            WAITG(0);
            __syncthreads();
        }
    }
    __syncthreads();

    float* s_out = sm;
#pragma unroll
    for (int hs = 0; hs < 2; ++hs)
#pragma unroll
        for (int co = 0; co < 4; ++co) {
            float* p = s_out + ((hs * 4 + co) * 32 + lane) * SOP + t0;
            *reinterpret_cast<float2*>(p) = upk(acc[hs][co][0]);
            if (t0 + 2 < TT)
                *reinterpret_cast<float2*>(p + 2) = upk(acc[hs][co][1]);
        }
    __syncthreads();

    // fused spike + next-layer psp epilogue: 256 pixels
    if (tid < 256) {
        float* row = s_out + tid * SOP;
        float sd1 = 0.f, sd2 = 0.f, sp1 = 0.f, sp2 = 0.f;
#pragma unroll
        for (int t = 0; t < TT; ++t) {
            float m = fmaf(cR, sd2, row[t]);
            float s = (m >= theta) ? 1.f : 0.f;
            sd1 = fmaf(rR, sd1, s);
            sd2 = fmaf(rR, sd2, rR * sd1);
            row[t] = cP * sp2;
            sp1 = fmaf(rP, sp1, s);
            sp2 = fmaf(rP, sp2, rP * sp1);
        }
    }
    __syncthreads();

    // coalesced store into padded bufB
    if (lane < 25) {
#pragma unroll
        for (int hs = 0; hs < 2; ++hs)
#pragma unroll
            for (int co = 0; co < 4; ++co) {
                const float2* s2 = reinterpret_cast<const float2*>(
                    s_out + (hs * 4 + co) * 32 * SOP);
                float2* g2 = reinterpret_cast<float2*>(out +
                    (((long)(n * CHN + co) * BW2 + h0 + hs + 1) * BW2 +
                     (w0 + 1)) * TT);
#pragma unroll
                for (int rr = 0; rr < 3; ++rr) {
                    const int w = wrp + rr * 13;
                    if (w < 32) g2[w * (TT / 2) + lane] = s2[w * (SOP / 2) + lane];
                }
            }
    }
}

// ---------------------------------------------------------------------------
// conv3 + spike-out: R14 2-row t-quad, 3-stage cp.async ring, occ 2.
// ---------------------------------------------------------------------------
__global__ void __launch_bounds__(416, 2)
conv3_kernel(const float* __restrict__ in, float* __restrict__ out,
             float rR, float cR, float theta) {
    constexpr int K     = 3;
    constexpr int WH    = 34;
    constexpr int NR    = 4;
    constexpr int STAGE = NR * WH * TP;

    extern __shared__ float sm[];
    const unsigned smem_base = (unsigned)__cvta_generic_to_shared(sm);

    const int tid  = threadIdx.x;
    const int lane = tid & 31;
    const int wrp  = tid >> 5;
    const int w0   = blockIdx.x * 32;
    const int h0   = blockIdx.y * 2;
    const int n    = blockIdx.z;
    const int t0   = wrp * 4;

    auto fill = [&](int buf, int ci) {
        if (lane < 25) {
            const unsigned dstb = smem_base + buf * (STAGE * 4) + lane * 8;
            const int nc = n * CHN + ci;
#pragma unroll
            for (int r = 0; r < NR; ++r) {
                const char* srcb = (const char*)(in +
                    (((long)nc * BW2 + h0 + r) * BW2 + w0) * TT) + lane * 8;
#pragma unroll
                for (int rr = 0; rr < 3; ++rr) {
                    const int wr = wrp + rr * 13;
                    if (wr < WH) {
                        asm volatile("cp.async.ca.shared.global [%0], [%1], 8;"
                                     :: "r"(dstb + (r * WH + wr) * (TP * 4)),
                                        "l"(srcb + wr * (TT * 4)) : "memory");
                    }
                }
            }
        }
        asm volatile("cp.async.commit_group;" ::: "memory");
    };

    u64 acc[2][4][2];
#pragma unroll
    for (int s = 0; s < 2; ++s)
#pragma unroll
        for (int c = 0; c < 4; ++c) { acc[s][c][0] = 0ull; acc[s][c][1] = 0ull; }

    auto compute = [&](const float* s_in, int ci) {
#pragma unroll
        for (int kw = 0; kw < K; ++kw) {
            const float* colp = s_in + (lane + kw) * TP + t0;
            ulonglong2 iv[NR];
#pragma unroll
            for (int r = 0; r < NR; ++r)
                iv[r] = *reinterpret_cast<const ulonglong2*>(colp + r * WH * TP);
#pragma unroll
            for (int r = 0; r < NR; ++r) {
                if (r < K) {
                    const int tap = (ci * K + r) * K + kw;
                    const ulonglong2 wa = cwload<3>(tap * 2);
                    const ulonglong2 wb = cwload<3>(tap * 2 + 1);
                    fma2(acc[0][0][0], iv[r].x, wa.x);
                    fma2(acc[0][0][1], iv[r].y, wa.x);
                    fma2(acc[0][1][0], iv[r].x, wa.y);
                    fma2(acc[0][1][1], iv[r].y, wa.y);
                    fma2(acc[0][2][0], iv[r].x, wb.x);
                    fma2(acc[0][2][1], iv[r].y, wb.x);
                    fma2(acc[0][3][0], iv[r].x, wb.y);
                    fma2(acc[0][3][1], iv[r].y, wb.y);
                }
                if (r >= 1) {
                    const int tap = (ci * K + (r - 1)) * K + kw;
                    const ulonglong2 wa = cwload<3>(tap * 2);
                    const ulonglong2 wb = cwload<3>(tap * 2 + 1);
                    fma2(acc[1][0][0], iv[r].x, wa.x);
                    fma2(acc[1][0][1], iv[r].y, wa.x);
                    fma2(acc[1][1][0], iv[r].x, wa.y);
                    fma2(acc[1][1][1], iv[r].y, wa.y);
                    fma2(acc[1][2][0], iv[r].x, wb.x);
                    fma2(acc[1][2][1], iv[r].y, wb.x);
                    fma2(acc[1][3][0], iv[r].x, wb.y);
                    fma2(acc[1][3][1], iv[r].y, wb.y);
                }
            }
        }
    };

    fill(0, 0);
    fill(1, 1);
    WAITG(1);
    __syncthreads();
#pragma unroll
    for (int ci = 0; ci < CHN; ++ci) {
        if (ci + 2 < CHN) fill((ci + 2) % 3, ci + 2);
        compute(sm + (ci % 3) * STAGE, ci);
        if (ci < CHN - 1) {
            if (ci + 2 < CHN) WAITG(1);
            else              WAITG(0);
            __syncthreads();
        }
    }
    __syncthreads();

    float* s_out = sm;
#pragma unroll
    for (int hs = 0; hs < 2; ++hs)
#pragma unroll
        for (int co = 0; co < 4; ++co) {
            float* p = s_out + ((hs * 4 + co) * 32 + lane) * SOP + t0;
            *reinterpret_cast<float2*>(p) = upk(acc[hs][co][0]);
            if (t0 + 2 < TT)
                *reinterpret_cast<float2*>(p + 2) = upk(acc[hs][co][1]);
        }
    __syncthreads();

    if (tid < 256) {
        float* row = s_out + tid * SOP;
        float sd1 = 0.f, sd2 = 0.f;
#pragma unroll
        for (int t = 0; t < TT; ++t) {
            float m = fmaf(cR, sd2, row[t]);
            float s = (m >= theta) ? 1.f : 0.f;
            sd1 = fmaf(rR, sd1, s);
            sd2 = fmaf(rR, sd2, rR * sd1);
            row[t] = s;
        }
    }
    __syncthreads();

    if (lane < 25) {
#pragma unroll
        for (int hs = 0; hs < 2; ++hs)
#pragma unroll
            for (int co = 0; co < 4; ++co) {
                const float2* s2 = reinterpret_cast<const float2*>(
                    s_out + (hs * 4 + co) * 32 * SOP);
                float2* g2 = reinterpret_cast<float2*>(out +
                    (((long)(n * CHN + co) * HHT + h0 + hs) * WWD + w0) * TT);
#pragma unroll
                for (int rr = 0; rr < 3; ++rr) {
                    const int w = wrp + rr * 13;
                    if (w < 32) g2[w * (TT / 2) + lane] = s2[w * (SOP / 2) + lane];
                }
            }
    }
}

// ---------------------------------------------------------------------------

extern "C" void kernel_launch(void* const* d_in, const int* in_sizes, int n_in,
                              void* d_out, int out_size) {
    const float* x  = (const float*)d_in[0];
    const float* w1 = (const float*)d_in[1];
    const float* w2 = (const float*)d_in[2];
    float* outp = (float*)d_out;

    float *bufA, *bufB;
    cudaGetSymbolAddress((void**)&bufA, g_bufA);
    cudaGetSymbolAddress((void**)&bufB, g_bufB);
    float4* wpack;
    cudaGetSymbolAddress((void**)&wpack, g_wpack);

    const int SMEM5 = 2 * 6 * 36 * TP * 4;   // 89856 B -> 2 blocks/SM
    const int SMEM3 = 3 * 4 * 34 * TP * 4;   // 84864 B -> 2 blocks/SM
    cudaFuncSetAttribute((const void*)conv5_kernel,
                         cudaFuncAttributeMaxDynamicSharedMemorySize, SMEM5);
    cudaFuncSetAttribute((const void*)conv3_kernel,
                         cudaFuncAttributeMaxDynamicSharedMemorySize, SMEM3);

    const float r1  = (float)0.36787944117144233;   // exp(-1/tau1)
    const float cP1 = (float)2.718281828459045;     // e/tau1
    const float rR1 = (float)0.36787944117144233;   // exp(-1/tauRef1)
    const float cR1 = (float)(-54.365636569180902); // -scaleRef*theta1*e/tauRef1
    const float th1 = 20.0f;
    const float r2  = (float)0.6065306597126334;    // exp(-1/tau2)
    const float cP2 = (float)1.3591409142295225;    // e/tau2
    const float rR2 = (float)0.6065306597126334;    // exp(-1/tauRef2)
    const float cR2 = (float)(-54.365636569180902); // -scaleRef*theta2*e/tauRef2
    const float th2 = 40.0f;

    dim3 pgrid(HHT, NPLANE);                    // (128, 32)
    dim3 cgrid(WWD / 32, HHT / 2, NBATCH);      // (4,64,8) = 2048 blocks

    setup_kernel<<<513, 256>>>(w1, w2);         // weights + parallel halo zero
    cudaMemcpyToSymbolAsync(c_w5d, wpack, 200 * sizeof(float4), 0,
                            cudaMemcpyDeviceToDevice, 0);
    cudaMemcpyToSymbolAsync(c_w3d, wpack + 200, 72 * sizeof(float4), 0,
                            cudaMemcpyDeviceToDevice, 0);

    psp_kernel<<<pgrid, 128>>>(x, bufA, r1, cP1);
    conv5_kernel<<<cgrid, 416, SMEM5>>>(bufA, bufB, rR1, cR1, th1, r2, cP2);
    conv3_kernel<<<cgrid, 416, SMEM3>>>(bufB, outp, rR2, cR2, th2);
}